// round 6
// baseline (speedup 1.0000x reference)
#include <cuda_runtime.h>
#include <cuda_bf16.h>

#define N_NODES 100000
#define N_EDGES 3200000
#define IN_F    128
#define HID     16
#define OUT_F   64
#define XB      256
#define FULL    0xffffffffu
#define NPB     1024                      // nodes per scan block
#define NB      ((N_NODES + NPB - 1) / NPB)

// ---- scratch ----
__device__ int   g_deg[2 * N_NODES];      // [0,N): out-degree, [N,2N): in-degree
__device__ float g_norm_src[N_NODES];
__device__ float g_norm_dst[N_NODES];
__device__ int   g_row_start[N_NODES + 4];
__device__ int   g_cursor[N_NODES];
__device__ int   g_blocksum[NB + 1];
__device__ int   g_csr_src[N_EDGES];
__device__ float4 g_y1[N_NODES * 4];
__device__ float4 g_y2[N_NODES * 4];

// ---- degree histograms (4 edges/thread) ----
__global__ void k_hist(const int* __restrict__ src, const int* __restrict__ dst, int e4) {
    int i = blockIdx.x * blockDim.x + threadIdx.x;
    if (i >= e4) return;
    int4 s = reinterpret_cast<const int4*>(src)[i];
    int4 d = reinterpret_cast<const int4*>(dst)[i];
    atomicAdd(&g_deg[s.x], 1); atomicAdd(&g_deg[s.y], 1);
    atomicAdd(&g_deg[s.z], 1); atomicAdd(&g_deg[s.w], 1);
    atomicAdd(&g_deg[N_NODES + d.x], 1); atomicAdd(&g_deg[N_NODES + d.y], 1);
    atomicAdd(&g_deg[N_NODES + d.z], 1); atomicAdd(&g_deg[N_NODES + d.w], 1);
}

// ---- scan A: per-block (1024-node) sums of in-degree; 256 thr, shfl reduce ----
__global__ void __launch_bounds__(256) k_scan1(int n) {
    __shared__ int sw[8];
    int t = threadIdx.x;
    int base4 = blockIdx.x * 256 + t;             // int4 index
    int4 d = make_int4(0, 0, 0, 0);
    if (base4 * 4 < n)
        d = reinterpret_cast<const int4*>(g_deg + N_NODES)[base4];
    int s = d.x + d.y + d.z + d.w;
    #pragma unroll
    for (int o = 16; o > 0; o >>= 1) s += __shfl_down_sync(FULL, s, o);
    if ((t & 31) == 0) sw[t >> 5] = s;
    __syncthreads();
    if (t < 8) {
        int v = sw[t];
        #pragma unroll
        for (int o = 4; o > 0; o >>= 1) v += __shfl_down_sync(FULL, v, o);
        if (t == 0) g_blocksum[blockIdx.x] = v;
    }
}

// ---- scan B: exclusive scan of NB block sums (1 block, 128 thr, shfl) ----
__global__ void __launch_bounds__(128) k_scan2(int e) {
    __shared__ int sw[4];
    int t = threadIdx.x;
    int v = (t < NB) ? g_blocksum[t] : 0;
    int inc = v;
    #pragma unroll
    for (int o = 1; o < 32; o <<= 1) {
        int w = __shfl_up_sync(FULL, inc, o);
        if ((t & 31) >= o) inc += w;
    }
    if ((t & 31) == 31) sw[t >> 5] = inc;
    __syncthreads();
    int woff = 0;
    int wid = t >> 5;
    if (wid >= 1) woff += sw[0];
    if (wid >= 2) woff += sw[1];
    if (wid >= 3) woff += sw[2];
    if (t < NB) g_blocksum[t] = inc - v + woff;   // exclusive
    if (t == 0) g_row_start[N_NODES] = e;
}

// ---- scan C: row_start/cursor via shfl scans; fused norms ----
__global__ void __launch_bounds__(256) k_scan3(int n) {
    __shared__ int sw[8];
    int t = threadIdx.x;
    int base4 = blockIdx.x * 256 + t;
    int node0 = base4 * 4;
    int4 din = make_int4(0, 0, 0, 0), dout = make_int4(0, 0, 0, 0);
    if (node0 < n) {
        din  = reinterpret_cast<const int4*>(g_deg + N_NODES)[base4];
        dout = reinterpret_cast<const int4*>(g_deg)[base4];
    }
    int s = din.x + din.y + din.z + din.w;
    int inc = s;
    #pragma unroll
    for (int o = 1; o < 32; o <<= 1) {
        int w = __shfl_up_sync(FULL, inc, o);
        if ((t & 31) >= o) inc += w;
    }
    if ((t & 31) == 31) sw[t >> 5] = inc;
    __syncthreads();
    int off = g_blocksum[blockIdx.x] + inc - s;   // exclusive within block
    int wid = t >> 5;
    #pragma unroll
    for (int w = 0; w < 7; w++)
        if (wid > w) off += sw[w];
    if (node0 < n) {
        int4 rs;
        rs.x = off;
        rs.y = rs.x + din.x;
        rs.z = rs.y + din.y;
        rs.w = rs.z + din.z;
        reinterpret_cast<int4*>(g_row_start)[base4] = rs;
        reinterpret_cast<int4*>(g_cursor)[base4]    = rs;
        float4 ns, nd;
        ns.x = rsqrtf((float)max(dout.x, 1)); ns.y = rsqrtf((float)max(dout.y, 1));
        ns.z = rsqrtf((float)max(dout.z, 1)); ns.w = rsqrtf((float)max(dout.w, 1));
        nd.x = rsqrtf((float)max(din.x, 1));  nd.y = rsqrtf((float)max(din.y, 1));
        nd.z = rsqrtf((float)max(din.z, 1));  nd.w = rsqrtf((float)max(din.w, 1));
        reinterpret_cast<float4*>(g_norm_src)[base4] = ns;
        reinterpret_cast<float4*>(g_norm_dst)[base4] = nd;
    }
}

// ---- CSR placement ----
__global__ void k_place(const int* __restrict__ src, const int* __restrict__ dst, int e) {
    int i = blockIdx.x * blockDim.x + threadIdx.x;
    if (i < e) {
        int pos = atomicAdd(&g_cursor[dst[i]], 1);
        g_csr_src[pos] = src[i];
    }
}

// ---- layer1 transform ----
__global__ void __launch_bounds__(XB) k_xform(const float* __restrict__ x,
                                              const float* __restrict__ W1, int n) {
    __shared__ float sW[IN_F * HID];
    __shared__ float sX[XB * 33];
    int t = threadIdx.x;
    for (int i = t; i < IN_F * HID / 4; i += XB)
        reinterpret_cast<float4*>(sW)[i] = reinterpret_cast<const float4*>(W1)[i];
    int base = blockIdx.x * XB;
    float acc[HID];
    #pragma unroll
    for (int j = 0; j < HID; j++) acc[j] = 0.f;
    for (int kc = 0; kc < IN_F; kc += 32) {
        __syncthreads();
        for (int i = t; i < XB * 8; i += XB) {
            int node = i >> 3, c4 = i & 7;
            float4 v = make_float4(0.f, 0.f, 0.f, 0.f);
            if (base + node < n)
                v = *reinterpret_cast<const float4*>(
                        x + (size_t)(base + node) * IN_F + kc + c4 * 4);
            float* dp = &sX[node * 33 + c4 * 4];
            dp[0] = v.x; dp[1] = v.y; dp[2] = v.z; dp[3] = v.w;
        }
        __syncthreads();
        const float* xr = &sX[t * 33];
        #pragma unroll
        for (int kk = 0; kk < 32; kk++) {
            float xk = xr[kk];
            const float4* wr = reinterpret_cast<const float4*>(&sW[(kc + kk) * HID]);
            float4 w0 = wr[0], w1 = wr[1], w2 = wr[2], w3 = wr[3];
            acc[0]  = fmaf(xk, w0.x, acc[0]);  acc[1]  = fmaf(xk, w0.y, acc[1]);
            acc[2]  = fmaf(xk, w0.z, acc[2]);  acc[3]  = fmaf(xk, w0.w, acc[3]);
            acc[4]  = fmaf(xk, w1.x, acc[4]);  acc[5]  = fmaf(xk, w1.y, acc[5]);
            acc[6]  = fmaf(xk, w1.z, acc[6]);  acc[7]  = fmaf(xk, w1.w, acc[7]);
            acc[8]  = fmaf(xk, w2.x, acc[8]);  acc[9]  = fmaf(xk, w2.y, acc[9]);
            acc[10] = fmaf(xk, w2.z, acc[10]); acc[11] = fmaf(xk, w2.w, acc[11]);
            acc[12] = fmaf(xk, w3.x, acc[12]); acc[13] = fmaf(xk, w3.y, acc[13]);
            acc[14] = fmaf(xk, w3.z, acc[14]); acc[15] = fmaf(xk, w3.w, acc[15]);
        }
    }
    int node = base + t;
    if (node >= n) return;
    float ns = g_norm_src[node];
    float4* op = &g_y1[node * 4];
    #pragma unroll
    for (int q = 0; q < 4; q++)
        op[q] = make_float4(acc[q*4]*ns, acc[q*4+1]*ns, acc[q*4+2]*ns, acc[q*4+3]*ns);
}

// ---- lane-per-edge aggregation: each lane loads whole 64B rows (MLP 4/lane),
//      then reduce-scatter so lane l holds feature (l & 15). ----
__device__ __forceinline__ float lane_aggregate(const float4* __restrict__ y,
                                                int beg, int end, int lane) {
    float v[16];
    #pragma unroll
    for (int j = 0; j < 16; j++) v[j] = 0.f;
    for (int i = beg + lane; i < end; i += 32) {
        int s = g_csr_src[i];                      // coalesced 128B per warp
        const float4* yr = &y[s * 4];
        float4 a0 = yr[0], a1 = yr[1], a2 = yr[2], a3 = yr[3];   // 4 indep LDG.128
        v[0]  += a0.x; v[1]  += a0.y; v[2]  += a0.z; v[3]  += a0.w;
        v[4]  += a1.x; v[5]  += a1.y; v[6]  += a1.z; v[7]  += a1.w;
        v[8]  += a2.x; v[9]  += a2.y; v[10] += a2.z; v[11] += a2.w;
        v[12] += a3.x; v[13] += a3.y; v[14] += a3.z; v[15] += a3.w;
    }
    // reduce-scatter: offsets 8,4,2,1 (keeps identity lane->feature), then dup-merge 16
    #pragma unroll
    for (int o = 8, L = 16; o >= 1; o >>= 1, L >>= 1) {
        int half = L >> 1;
        bool hi = (lane & o) != 0;
        #pragma unroll
        for (int j = 0; j < 8; j++) {
            if (j >= half) break;
            float send = hi ? v[j] : v[half + j];
            float recv = __shfl_xor_sync(FULL, send, o);
            v[j] = (hi ? v[half + j] : v[j]) + recv;
        }
    }
    v[0] += __shfl_xor_sync(FULL, v[0], 16);
    return v[0];                                   // feature (lane & 15)
}

// ---- gather layer 1: y2[f] = relu(agg*nd + b1[f]) * ns ----
__global__ void __launch_bounds__(256) k_gather1(const float* __restrict__ b1, int n) {
    int warp = (blockIdx.x * blockDim.x + threadIdx.x) >> 5;
    if (warp >= n) return;
    int lane = threadIdx.x & 31;
    int beg = g_row_start[warp], end = g_row_start[warp + 1];
    float a = lane_aggregate(g_y1, beg, end, lane);
    if (lane < 16) {
        float nd = g_norm_dst[warp], ns = g_norm_src[warp];
        float r = fmaxf(fmaf(a, nd, __ldg(&b1[lane])), 0.f) * ns;
        reinterpret_cast<float*>(g_y2)[warp * HID + lane] = r;   // 64B coalesced
    }
}

// ---- gather layer 2 + final matmul: out = (agg @ W2) * nd + b2 ----
__global__ void __launch_bounds__(256) k_gather2(const float* __restrict__ W2,
                                                 const float* __restrict__ b2,
                                                 float* __restrict__ out, int n) {
    __shared__ float sW2[HID * OUT_F];
    __shared__ float sB2[OUT_F];
    int t = threadIdx.x;
    for (int i = t; i < HID * OUT_F / 4; i += 256)
        reinterpret_cast<float4*>(sW2)[i] = reinterpret_cast<const float4*>(W2)[i];
    if (t < OUT_F) sB2[t] = b2[t];
    __syncthreads();

    int warp = (blockIdx.x * blockDim.x + t) >> 5;
    if (warp >= n) return;
    int lane = t & 31;
    int beg = g_row_start[warp], end = g_row_start[warp + 1];
    float av = lane_aggregate(g_y2, beg, end, lane);
    // broadcast 16 features to all lanes
    float a[HID];
    #pragma unroll
    for (int k = 0; k < HID; k++) a[k] = __shfl_sync(FULL, av, k);
    float o0 = 0.f, o1 = 0.f;
    const float2* w2v = reinterpret_cast<const float2*>(sW2);
    #pragma unroll
    for (int k = 0; k < HID; k++) {
        float2 w = w2v[k * (OUT_F / 2) + lane];
        o0 = fmaf(a[k], w.x, o0);
        o1 = fmaf(a[k], w.y, o1);
    }
    float nd = g_norm_dst[warp];
    float2 bb = reinterpret_cast<const float2*>(sB2)[lane];
    reinterpret_cast<float2*>(out)[warp * (OUT_F / 2) + lane] =
        make_float2(fmaf(o0, nd, bb.x), fmaf(o1, nd, bb.y));
}

extern "C" void kernel_launch(void* const* d_in, const int* in_sizes, int n_in,
                              void* d_out, int out_size) {
    const float* x   = (const float*)d_in[0];
    const int*   src = (const int*)  d_in[1];
    const int*   dst = (const int*)  d_in[2];
    const float* W1  = (const float*)d_in[3];
    const float* b1  = (const float*)d_in[4];
    const float* W2  = (const float*)d_in[5];
    const float* b2  = (const float*)d_in[6];
    float* out = (float*)d_out;

    int n = in_sizes[0] / IN_F;    // 100000
    int e = in_sizes[1];           // 3200000

    void* p_deg = nullptr;
    cudaGetSymbolAddress(&p_deg, g_deg);
    cudaMemsetAsync(p_deg, 0, 2 * N_NODES * sizeof(int));

    const int T = 256;
    int e4 = e / 4;
    k_hist  <<<(e4 + T - 1) / T, T>>>(src, dst, e4);
    k_scan1 <<<NB, 256>>>(n);
    k_scan2 <<<1, 128>>>(e);
    k_scan3 <<<NB, 256>>>(n);
    k_place <<<(e + T - 1) / T, T>>>(src, dst, e);
    k_xform <<<(n + XB - 1) / XB, XB>>>(x, W1, n);
    k_gather1<<<(n * 32 + T - 1) / T, T>>>(b1, n);
    k_gather2<<<(n * 32 + T - 1) / T, T>>>(W2, b2, out, n);
}

// round 7
// speedup vs baseline: 1.2953x; 1.2953x over previous
#include <cuda_runtime.h>
#include <cuda_bf16.h>

#define N_NODES 100000
#define N_EDGES 3200000
#define IN_F    128
#define HID     16
#define OUT_F   64
#define XB      256
#define FULL    0xffffffffu
#define NPB     1024                      // nodes per scan block
#define NB      ((N_NODES + NPB - 1) / NPB)

// ---- scratch ----
__device__ int   g_deg[2 * N_NODES];      // [0,N): out-degree, [N,2N): in-degree
__device__ float g_norm_src[N_NODES];
__device__ float g_norm_dst[N_NODES];
__device__ int   g_row_start[N_NODES + 4];
__device__ int   g_cursor[N_NODES];
__device__ int   g_blocksum[NB + 1];
__device__ int   g_csr_src[N_EDGES];
__device__ float4 g_y1[N_NODES * 4];
__device__ float4 g_y2[N_NODES * 4];

// ---- degree histograms (4 edges/thread) ----
__global__ void k_hist(const int* __restrict__ src, const int* __restrict__ dst, int e4) {
    int i = blockIdx.x * blockDim.x + threadIdx.x;
    if (i >= e4) return;
    int4 s = reinterpret_cast<const int4*>(src)[i];
    int4 d = reinterpret_cast<const int4*>(dst)[i];
    atomicAdd(&g_deg[s.x], 1); atomicAdd(&g_deg[s.y], 1);
    atomicAdd(&g_deg[s.z], 1); atomicAdd(&g_deg[s.w], 1);
    atomicAdd(&g_deg[N_NODES + d.x], 1); atomicAdd(&g_deg[N_NODES + d.y], 1);
    atomicAdd(&g_deg[N_NODES + d.z], 1); atomicAdd(&g_deg[N_NODES + d.w], 1);
}

// ---- scan A: per-block (1024-node) sums of in-degree ----
__global__ void __launch_bounds__(256) k_scan1(int n) {
    __shared__ int sw[8];
    int t = threadIdx.x;
    int base4 = blockIdx.x * 256 + t;
    int4 d = make_int4(0, 0, 0, 0);
    if (base4 * 4 < n)
        d = reinterpret_cast<const int4*>(g_deg + N_NODES)[base4];
    int s = d.x + d.y + d.z + d.w;
    #pragma unroll
    for (int o = 16; o > 0; o >>= 1) s += __shfl_down_sync(FULL, s, o);
    if ((t & 31) == 0) sw[t >> 5] = s;
    __syncthreads();
    if (t < 8) {
        int v = sw[t];
        #pragma unroll
        for (int o = 4; o > 0; o >>= 1) v += __shfl_down_sync(FULL, v, o);
        if (t == 0) g_blocksum[blockIdx.x] = v;
    }
}

// ---- scan B: exclusive scan of NB block sums ----
__global__ void __launch_bounds__(128) k_scan2(int e) {
    __shared__ int sw[4];
    int t = threadIdx.x;
    int v = (t < NB) ? g_blocksum[t] : 0;
    int inc = v;
    #pragma unroll
    for (int o = 1; o < 32; o <<= 1) {
        int w = __shfl_up_sync(FULL, inc, o);
        if ((t & 31) >= o) inc += w;
    }
    if ((t & 31) == 31) sw[t >> 5] = inc;
    __syncthreads();
    int woff = 0;
    int wid = t >> 5;
    if (wid >= 1) woff += sw[0];
    if (wid >= 2) woff += sw[1];
    if (wid >= 3) woff += sw[2];
    if (t < NB) g_blocksum[t] = inc - v + woff;
    if (t == 0) g_row_start[N_NODES] = e;
}

// ---- scan C: row_start/cursor + fused norms ----
__global__ void __launch_bounds__(256) k_scan3(int n) {
    __shared__ int sw[8];
    int t = threadIdx.x;
    int base4 = blockIdx.x * 256 + t;
    int node0 = base4 * 4;
    int4 din = make_int4(0, 0, 0, 0), dout = make_int4(0, 0, 0, 0);
    if (node0 < n) {
        din  = reinterpret_cast<const int4*>(g_deg + N_NODES)[base4];
        dout = reinterpret_cast<const int4*>(g_deg)[base4];
    }
    int s = din.x + din.y + din.z + din.w;
    int inc = s;
    #pragma unroll
    for (int o = 1; o < 32; o <<= 1) {
        int w = __shfl_up_sync(FULL, inc, o);
        if ((t & 31) >= o) inc += w;
    }
    if ((t & 31) == 31) sw[t >> 5] = inc;
    __syncthreads();
    int off = g_blocksum[blockIdx.x] + inc - s;
    int wid = t >> 5;
    #pragma unroll
    for (int w = 0; w < 7; w++)
        if (wid > w) off += sw[w];
    if (node0 < n) {
        int4 rs;
        rs.x = off;
        rs.y = rs.x + din.x;
        rs.z = rs.y + din.y;
        rs.w = rs.z + din.z;
        reinterpret_cast<int4*>(g_row_start)[base4] = rs;
        reinterpret_cast<int4*>(g_cursor)[base4]    = rs;
        float4 ns, nd;
        ns.x = rsqrtf((float)max(dout.x, 1)); ns.y = rsqrtf((float)max(dout.y, 1));
        ns.z = rsqrtf((float)max(dout.z, 1)); ns.w = rsqrtf((float)max(dout.w, 1));
        nd.x = rsqrtf((float)max(din.x, 1));  nd.y = rsqrtf((float)max(din.y, 1));
        nd.z = rsqrtf((float)max(din.z, 1));  nd.w = rsqrtf((float)max(din.w, 1));
        reinterpret_cast<float4*>(g_norm_src)[base4] = ns;
        reinterpret_cast<float4*>(g_norm_dst)[base4] = nd;
    }
}

// ---- CSR placement ----
__global__ void k_place(const int* __restrict__ src, const int* __restrict__ dst, int e) {
    int i = blockIdx.x * blockDim.x + threadIdx.x;
    if (i < e) {
        int pos = atomicAdd(&g_cursor[dst[i]], 1);
        g_csr_src[pos] = src[i];
    }
}

// ---- layer1 transform ----
__global__ void __launch_bounds__(XB) k_xform(const float* __restrict__ x,
                                              const float* __restrict__ W1, int n) {
    __shared__ float sW[IN_F * HID];
    __shared__ float sX[XB * 33];
    int t = threadIdx.x;
    for (int i = t; i < IN_F * HID / 4; i += XB)
        reinterpret_cast<float4*>(sW)[i] = reinterpret_cast<const float4*>(W1)[i];
    int base = blockIdx.x * XB;
    float acc[HID];
    #pragma unroll
    for (int j = 0; j < HID; j++) acc[j] = 0.f;
    for (int kc = 0; kc < IN_F; kc += 32) {
        __syncthreads();
        for (int i = t; i < XB * 8; i += XB) {
            int node = i >> 3, c4 = i & 7;
            float4 v = make_float4(0.f, 0.f, 0.f, 0.f);
            if (base + node < n)
                v = *reinterpret_cast<const float4*>(
                        x + (size_t)(base + node) * IN_F + kc + c4 * 4);
            float* dp = &sX[node * 33 + c4 * 4];
            dp[0] = v.x; dp[1] = v.y; dp[2] = v.z; dp[3] = v.w;
        }
        __syncthreads();
        const float* xr = &sX[t * 33];
        #pragma unroll
        for (int kk = 0; kk < 32; kk++) {
            float xk = xr[kk];
            const float4* wr = reinterpret_cast<const float4*>(&sW[(kc + kk) * HID]);
            float4 w0 = wr[0], w1 = wr[1], w2 = wr[2], w3 = wr[3];
            acc[0]  = fmaf(xk, w0.x, acc[0]);  acc[1]  = fmaf(xk, w0.y, acc[1]);
            acc[2]  = fmaf(xk, w0.z, acc[2]);  acc[3]  = fmaf(xk, w0.w, acc[3]);
            acc[4]  = fmaf(xk, w1.x, acc[4]);  acc[5]  = fmaf(xk, w1.y, acc[5]);
            acc[6]  = fmaf(xk, w1.z, acc[6]);  acc[7]  = fmaf(xk, w1.w, acc[7]);
            acc[8]  = fmaf(xk, w2.x, acc[8]);  acc[9]  = fmaf(xk, w2.y, acc[9]);
            acc[10] = fmaf(xk, w2.z, acc[10]); acc[11] = fmaf(xk, w2.w, acc[11]);
            acc[12] = fmaf(xk, w3.x, acc[12]); acc[13] = fmaf(xk, w3.y, acc[13]);
            acc[14] = fmaf(xk, w3.z, acc[14]); acc[15] = fmaf(xk, w3.w, acc[15]);
        }
    }
    int node = base + t;
    if (node >= n) return;
    float ns = g_norm_src[node];
    float4* op = &g_y1[node * 4];
    #pragma unroll
    for (int q = 0; q < 4; q++)
        op[q] = make_float4(acc[q*4]*ns, acc[q*4+1]*ns, acc[q*4+2]*ns, acc[q*4+3]*ns);
}

// ---- grouped warp aggregation (R5 shape), unrolled x2: 16 edges in flight. ----
// lane = e_sub*4 + p; each 4-lane group reads one node's contiguous 64B (nL=8/instr),
// two independent edge batches per iteration (MLP 16/warp).
__device__ __forceinline__ float4 warp_aggregate(const float4* __restrict__ y,
                                                 int beg, int end, int e_sub, int p) {
    float4 acc0 = make_float4(0.f, 0.f, 0.f, 0.f);
    float4 acc1 = make_float4(0.f, 0.f, 0.f, 0.f);
    for (int i = beg; i < end; i += 16) {
        int i0 = i + e_sub;
        int i1 = i + 8 + e_sub;
        if (i0 < end) {
            int s0 = g_csr_src[i0];        // broadcast within 4-lane group
            float4 v = y[s0 * 4 + p];
            acc0.x += v.x; acc0.y += v.y; acc0.z += v.z; acc0.w += v.w;
        }
        if (i1 < end) {
            int s1 = g_csr_src[i1];
            float4 v = y[s1 * 4 + p];
            acc1.x += v.x; acc1.y += v.y; acc1.z += v.z; acc1.w += v.w;
        }
    }
    acc0.x += acc1.x; acc0.y += acc1.y; acc0.z += acc1.z; acc0.w += acc1.w;
    #pragma unroll
    for (int off = 16; off >= 4; off >>= 1) {
        acc0.x += __shfl_down_sync(FULL, acc0.x, off);
        acc0.y += __shfl_down_sync(FULL, acc0.y, off);
        acc0.z += __shfl_down_sync(FULL, acc0.z, off);
        acc0.w += __shfl_down_sync(FULL, acc0.w, off);
    }
    return acc0;   // valid on lanes 0..3 (lane == p)
}

// ---- gather layer 1: y2 = relu(agg(y1)*nd + b1) * ns ----
__global__ void __launch_bounds__(256) k_gather1(const float* __restrict__ b1, int n) {
    int warp = (blockIdx.x * blockDim.x + threadIdx.x) >> 5;
    if (warp >= n) return;
    int lane = threadIdx.x & 31;
    int e_sub = lane >> 2, p = lane & 3;
    int beg = g_row_start[warp], end = g_row_start[warp + 1];
    float4 acc = warp_aggregate(g_y1, beg, end, e_sub, p);
    if (lane < 4) {
        float nd = g_norm_dst[warp], ns = g_norm_src[warp];
        float4 bv = reinterpret_cast<const float4*>(b1)[p];
        acc.x = fmaxf(fmaf(acc.x, nd, bv.x), 0.f) * ns;
        acc.y = fmaxf(fmaf(acc.y, nd, bv.y), 0.f) * ns;
        acc.z = fmaxf(fmaf(acc.z, nd, bv.z), 0.f) * ns;
        acc.w = fmaxf(fmaf(acc.w, nd, bv.w), 0.f) * ns;
        g_y2[warp * 4 + p] = acc;
    }
}

// ---- gather layer 2 + final matmul: out = (agg @ W2) * nd + b2 ----
__global__ void __launch_bounds__(256) k_gather2(const float* __restrict__ W2,
                                                 const float* __restrict__ b2,
                                                 float* __restrict__ out, int n) {
    __shared__ float sW2[HID * OUT_F];
    __shared__ float sB2[OUT_F];
    int t = threadIdx.x;
    for (int i = t; i < HID * OUT_F / 4; i += 256)
        reinterpret_cast<float4*>(sW2)[i] = reinterpret_cast<const float4*>(W2)[i];
    if (t < OUT_F) sB2[t] = b2[t];
    __syncthreads();

    int warp = (blockIdx.x * blockDim.x + t) >> 5;
    if (warp >= n) return;
    int lane = t & 31;
    int e_sub = lane >> 2, p = lane & 3;
    int beg = g_row_start[warp], end = g_row_start[warp + 1];
    float4 acc = warp_aggregate(g_y2, beg, end, e_sub, p);

    // broadcast 16 agg features (lanes 0..3 hold parts 0..3) to all lanes
    float a[HID];
    #pragma unroll
    for (int q = 0; q < 4; q++) {
        a[q*4+0] = __shfl_sync(FULL, acc.x, q);
        a[q*4+1] = __shfl_sync(FULL, acc.y, q);
        a[q*4+2] = __shfl_sync(FULL, acc.z, q);
        a[q*4+3] = __shfl_sync(FULL, acc.w, q);
    }
    float o0 = 0.f, o1 = 0.f;
    const float2* w2v = reinterpret_cast<const float2*>(sW2);
    #pragma unroll
    for (int k = 0; k < HID; k++) {
        float2 w = w2v[k * (OUT_F / 2) + lane];
        o0 = fmaf(a[k], w.x, o0);
        o1 = fmaf(a[k], w.y, o1);
    }
    float nd = g_norm_dst[warp];
    float2 bb = reinterpret_cast<const float2*>(sB2)[lane];
    reinterpret_cast<float2*>(out)[warp * (OUT_F / 2) + lane] =
        make_float2(fmaf(o0, nd, bb.x), fmaf(o1, nd, bb.y));
}

extern "C" void kernel_launch(void* const* d_in, const int* in_sizes, int n_in,
                              void* d_out, int out_size) {
    const float* x   = (const float*)d_in[0];
    const int*   src = (const int*)  d_in[1];
    const int*   dst = (const int*)  d_in[2];
    const float* W1  = (const float*)d_in[3];
    const float* b1  = (const float*)d_in[4];
    const float* W2  = (const float*)d_in[5];
    const float* b2  = (const float*)d_in[6];
    float* out = (float*)d_out;

    int n = in_sizes[0] / IN_F;    // 100000
    int e = in_sizes[1];           // 3200000

    void* p_deg = nullptr;
    cudaGetSymbolAddress(&p_deg, g_deg);
    cudaMemsetAsync(p_deg, 0, 2 * N_NODES * sizeof(int));

    const int T = 256;
    int e4 = e / 4;
    k_hist  <<<(e4 + T - 1) / T, T>>>(src, dst, e4);
    k_scan1 <<<NB, 256>>>(n);
    k_scan2 <<<1, 128>>>(e);
    k_scan3 <<<NB, 256>>>(n);
    k_place <<<(e + T - 1) / T, T>>>(src, dst, e);
    k_xform <<<(n + XB - 1) / XB, XB>>>(x, W1, n);
    k_gather1<<<(n * 32 + T - 1) / T, T>>>(b1, n);
    k_gather2<<<(n * 32 + T - 1) / T, T>>>(W2, b2, out, n);
}